// round 1
// baseline (speedup 1.0000x reference)
#include <cuda_runtime.h>
#include <cuda_bf16.h>

#define Bb 256
#define Ss 512
#define Vv 50000
#define Dd 256
#define Ll 128
#define PAD_T 0
#define BOS_T 1
#define EOS_T 2

// ---------------- device scratch (no allocations allowed) ----------------
__device__ float  g_embW[Vv * Dd];   // emb @ Wout  (51.2 MB)
__device__ float  g_enc[Bb * Dd];
__device__ float  g_c[Bb * Dd];      // memory @ Wout + bout, per batch
__device__ int    g_len[Bb];
__device__ int    g_mode;            // 0=int32 mask, 1=uint8 mask, 2=float32 mask
__device__ int    g_valid;           // total valid target count
__device__ double g_sq;              // sum of squared diffs
__device__ double g_kl;              // sum of (1+lv-mean^2-exp(lv))

// ---------------- K0: detect mask dtype + zero accumulators ----------------
__global__ void k0_detect(const unsigned* mask_words) {
    __shared__ int any_gt1, any_f32;
    if (threadIdx.x == 0) { any_gt1 = 0; any_f32 = 0; }
    __syncthreads();
    int bad = 0, f32 = 0;
    // scan only 32768 words = 128KB, valid under every dtype hypothesis
    for (int i = threadIdx.x; i < 32768; i += 256) {
        unsigned v = mask_words[i];
        if (v > 1u) { bad = 1; if (v == 0x3f800000u) f32 = 1; }
    }
    if (bad) atomicOr(&any_gt1, 1);
    if (f32) atomicOr(&any_f32, 1);
    __syncthreads();
    if (threadIdx.x == 0) {
        g_mode = any_gt1 ? (any_f32 ? 2 : 1) : 0;
        g_sq = 0.0; g_kl = 0.0; g_valid = 0;
    }
}

__device__ __forceinline__ int mask_at(const void* m, int idx, int mode) {
    if (mode == 0) return ((const int*)m)[idx] != 0;
    if (mode == 1) return ((const unsigned char*)m)[idx] != 0;
    return ((const float*)m)[idx] != 0.0f;
}

// ---------------- K4: embW = emb @ Wout  (50000x256 @ 256x256 fp32) -------
__global__ void gemm_embW(const float* __restrict__ emb,
                          const float* __restrict__ Wout) {
    __shared__ __align__(16) float sA[16][68];  // [k][m], padded
    __shared__ __align__(16) float sB[16][64];  // [k][n]
    const int tid = threadIdx.x;
    const int tx = tid & 15, ty = tid >> 4;
    const int row0 = blockIdx.x * 64;
    const int col0 = blockIdx.y * 64;

    const int lm  = tid >> 2;         // 0..63 (A row within tile)
    const int lk4 = (tid & 3) * 4;    // 0,4,8,12 (A k chunk)
    const int bk  = tid >> 4;         // 0..15 (B k)
    const int bn4 = (tid & 15) * 4;   // B n chunk

    float acc[4][4];
    #pragma unroll
    for (int i = 0; i < 4; i++)
        #pragma unroll
        for (int j = 0; j < 4; j++) acc[i][j] = 0.0f;

    for (int k0 = 0; k0 < 256; k0 += 16) {
        int gr = row0 + lm;
        float4 av = (gr < Vv) ? *(const float4*)(emb + (size_t)gr * Dd + k0 + lk4)
                              : make_float4(0.f, 0.f, 0.f, 0.f);
        sA[lk4 + 0][lm] = av.x;
        sA[lk4 + 1][lm] = av.y;
        sA[lk4 + 2][lm] = av.z;
        sA[lk4 + 3][lm] = av.w;
        *(float4*)&sB[bk][bn4] = *(const float4*)(Wout + (size_t)(k0 + bk) * Dd + col0 + bn4);
        __syncthreads();
        #pragma unroll
        for (int kk = 0; kk < 16; kk++) {
            float4 a = *(const float4*)&sA[kk][ty * 4];
            float4 b = *(const float4*)&sB[kk][tx * 4];
            float av_[4] = {a.x, a.y, a.z, a.w};
            float bv_[4] = {b.x, b.y, b.z, b.w};
            #pragma unroll
            for (int i = 0; i < 4; i++)
                #pragma unroll
                for (int j = 0; j < 4; j++)
                    acc[i][j] += av_[i] * bv_[j];
        }
        __syncthreads();
    }
    #pragma unroll
    for (int i = 0; i < 4; i++) {
        int gr = row0 + ty * 4 + i;
        if (gr < Vv) {
            float4 v = make_float4(acc[i][0], acc[i][1], acc[i][2], acc[i][3]);
            *(float4*)(g_embW + (size_t)gr * Dd + col0 + tx * 4) = v;
        }
    }
}

// ---------------- K2: enc[b,:] = masked mean of (emb[tok]+emb[parent]) ----
__global__ void enc_kernel(const int* __restrict__ vocab,
                           const int* __restrict__ order,
                           const void* __restrict__ mask,
                           const float* __restrict__ emb) {
    const int b = blockIdx.x;
    const int tid = threadIdx.x;
    const int w = tid >> 5, lane = tid & 31;
    const int mode = g_mode;

    __shared__ int sred[256];
    __shared__ int s_len;

    int cnt = 0;
    for (int i = tid; i < Ss; i += 256) cnt += mask_at(mask, b * Ss + i, mode);
    sred[tid] = cnt;
    __syncthreads();
    for (int st = 128; st > 0; st >>= 1) {
        if (tid < st) sred[tid] += sred[tid + st];
        __syncthreads();
    }
    if (tid == 0) {
        int len = sred[0];
        s_len = len;
        g_len[b] = len;
        int nb = (len < Ss) ? len + 1 : Ss + 1;
        atomicAdd(&g_valid, nb);
    }
    __syncthreads();
    const int len = s_len;

    float a0 = 0, a1 = 0, a2 = 0, a3 = 0, a4 = 0, a5 = 0, a6 = 0, a7 = 0;
    for (int s = w; s < len; s += 8) {
        int tok = vocab[b * Ss + s];
        int oi = order[(size_t)(b * Ss + s) * 6];
        if (oi == -1) oi = BOS_T;
        int p;
        if (s == 0) p = BOS_T;
        else        p = (oi < len) ? vocab[b * Ss + oi] : PAD_T;
        const float* r1 = emb + (size_t)tok * Dd + lane * 8;
        const float* r2 = emb + (size_t)p   * Dd + lane * 8;
        float4 x0 = *(const float4*)r1;
        float4 x1 = *(const float4*)(r1 + 4);
        float4 y0 = *(const float4*)r2;
        float4 y1 = *(const float4*)(r2 + 4);
        a0 += x0.x + y0.x; a1 += x0.y + y0.y; a2 += x0.z + y0.z; a3 += x0.w + y0.w;
        a4 += x1.x + y1.x; a5 += x1.y + y1.y; a6 += x1.z + y1.z; a7 += x1.w + y1.w;
    }
    __shared__ float s_acc[8][256];
    float* dst = &s_acc[w][lane * 8];
    dst[0] = a0; dst[1] = a1; dst[2] = a2; dst[3] = a3;
    dst[4] = a4; dst[5] = a5; dst[6] = a6; dst[7] = a7;
    __syncthreads();
    float v = 0;
    #pragma unroll
    for (int ww = 0; ww < 8; ww++) v += s_acc[ww][tid];
    g_enc[b * Dd + tid] = v / (float)len;   // len >= 1 always
}

// ---------------- K3: latent sampler + memory@Wout + kl -------------------
__global__ void latent_kernel(const float* __restrict__ eps,
                              const float* __restrict__ Wm, const float* __restrict__ bm,
                              const float* __restrict__ Wv, const float* __restrict__ bv,
                              const float* __restrict__ Wlin, const float* __restrict__ blin,
                              const float* __restrict__ Wout, const float* __restrict__ bout) {
    const int b = blockIdx.x, t = threadIdx.x;
    __shared__ float se[Dd];
    __shared__ float sz[Ll];
    __shared__ float sm_[Dd];
    __shared__ float skl[256];

    se[t] = g_enc[b * Dd + t];
    __syncthreads();

    float klp = 0.0f;
    if (t < Ll) {
        float mean = bm[t], lv = bv[t];
        #pragma unroll 4
        for (int d = 0; d < Dd; d++) {
            float e = se[d];
            mean += e * Wm[d * Ll + t];
            lv   += e * Wv[d * Ll + t];
        }
        float z = mean + eps[b * Ll + t] * expf(0.5f * lv);
        sz[t] = z;
        klp = 1.0f + lv - mean * mean - expf(lv);
    }
    skl[t] = klp;
    __syncthreads();
    for (int st = 128; st > 0; st >>= 1) {
        if (t < st) skl[t] += skl[t + st];
        __syncthreads();
    }
    if (t == 0) atomicAdd(&g_kl, (double)skl[0]);
    __syncthreads();

    float md = blin[t];
    #pragma unroll 4
    for (int l = 0; l < Ll; l++) md += sz[l] * Wlin[l * Dd + t];
    sm_[t] = md;
    __syncthreads();
    float cd = bout[t];
    #pragma unroll 4
    for (int k = 0; k < Dd; k++) cd += sm_[k] * Wout[k * Dd + t];
    g_c[b * Dd + t] = cd;
}

// ---------------- K5: token loss reduction --------------------------------
__global__ void loss_kernel(const int* __restrict__ vocab,
                            const float* __restrict__ emb) {
    const int b = blockIdx.x;
    const int chunk = blockIdx.y;   // 0..7
    const int tid = threadIdx.x;
    const int w = tid >> 5, lane = tid & 31;
    const int len = g_len[b];
    const int nb = (len < Ss) ? len + 1 : Ss + 1;

    const float* crow = g_c + b * Dd + lane * 8;
    float4 c0 = *(const float4*)crow;
    float4 c1 = *(const float4*)(crow + 4);

    float ss = 0.0f;
    for (int s = chunk * 8 + w; s < nb; s += 64) {
        int u = (s == 0) ? BOS_T : vocab[b * Ss + s - 1];
        int v;
        if (s < len) v = vocab[b * Ss + s];
        else         v = (len < Ss) ? EOS_T : BOS_T;   // roll-wrap when len==S
        const float* ap = g_embW + (size_t)u * Dd + lane * 8;
        const float* tp = emb    + (size_t)v * Dd + lane * 8;
        float4 x0 = *(const float4*)ap;
        float4 x1 = *(const float4*)(ap + 4);
        float4 y0 = *(const float4*)tp;
        float4 y1 = *(const float4*)(tp + 4);
        float d0 = x0.x + c0.x - y0.x; ss += d0 * d0;
        float d1 = x0.y + c0.y - y0.y; ss += d1 * d1;
        float d2 = x0.z + c0.z - y0.z; ss += d2 * d2;
        float d3 = x0.w + c0.w - y0.w; ss += d3 * d3;
        float d4 = x1.x + c1.x - y1.x; ss += d4 * d4;
        float d5 = x1.y + c1.y - y1.y; ss += d5 * d5;
        float d6 = x1.z + c1.z - y1.z; ss += d6 * d6;
        float d7 = x1.w + c1.w - y1.w; ss += d7 * d7;
    }
    // warp reduce
    #pragma unroll
    for (int off = 16; off > 0; off >>= 1)
        ss += __shfl_xor_sync(0xffffffffu, ss, off);
    __shared__ float swarp[8];
    if (lane == 0) swarp[w] = ss;
    __syncthreads();
    if (tid == 0) {
        double tot = 0.0;
        #pragma unroll
        for (int i = 0; i < 8; i++) tot += (double)swarp[i];
        atomicAdd(&g_sq, tot);
    }
}

// ---------------- K6: finalize ---------------------------------------------
__global__ void finalize_kernel(float* out) {
    if (threadIdx.x == 0) {
        long long denom = (long long)g_valid * (long long)Dd;
        if (denom < 1) denom = 1;
        out[0] = (float)(g_sq / (double)denom);
        out[1] = (float)(-0.5 * g_kl / (double)Bb);
    }
}

// ---------------- launch ----------------------------------------------------
extern "C" void kernel_launch(void* const* d_in, const int* in_sizes, int n_in,
                              void* d_out, int out_size) {
    (void)in_sizes; (void)n_in; (void)out_size;
    const int*   vocab = (const int*)d_in[0];
    const int*   order = (const int*)d_in[1];
    const void*  mask  = d_in[2];
    const float* eps   = (const float*)d_in[3];
    const float* emb   = (const float*)d_in[4];
    const float* Wm    = (const float*)d_in[5];
    const float* bm    = (const float*)d_in[6];
    const float* Wv    = (const float*)d_in[7];
    const float* bv    = (const float*)d_in[8];
    const float* Wlin  = (const float*)d_in[9];
    const float* blin  = (const float*)d_in[10];
    const float* Wout  = (const float*)d_in[11];
    const float* bout  = (const float*)d_in[12];
    float* out = (float*)d_out;

    k0_detect<<<1, 256>>>((const unsigned*)mask);
    gemm_embW<<<dim3((Vv + 63) / 64, Dd / 64), 256>>>(emb, Wout);
    enc_kernel<<<Bb, 256>>>(vocab, order, mask, emb);
    latent_kernel<<<Bb, 256>>>(eps, Wm, bm, Wv, bv, Wlin, blin, Wout, bout);
    loss_kernel<<<dim3(Bb, 8), 256>>>(vocab, emb);
    finalize_kernel<<<1, 32>>>(out);
}